// round 3
// baseline (speedup 1.0000x reference)
#include <cuda_runtime.h>
#include <cmath>

// Problem constants
#define B_    4096
#define IN_   1024
#define F_    512
#define HID_  128
#define D_    128
#define RH_   64
#define C_    10
#define R_    16
#define CH_   1280   // C_*HID_

// ---------------- device scratch ----------------
__device__ __align__(256) float g_w[R_][C_];
__device__ __align__(256) float g_rv[R_][D_];
__device__ __align__(256) float g_W2[R_][HID_];
__device__ __align__(256) float g_b1[R_][HID_];
__device__ __align__(256) float g_beff[R_];
__device__ __align__(256) float g_P[CH_][R_];        // P[ch][r] = w[r,c]*W2[r,h]
__device__ __align__(256) float g_Weff[R_][F_];
__device__ __align__(256) float g_WxPart[8][IN_][R_];
__device__ __align__(256) float g_WxT[IN_][R_];      // [i][r]
__device__ __align__(256) float g_cst[R_];

// ---------------- packed f32x2 helpers ----------------
__device__ __forceinline__ unsigned long long pk2(float a, float b) {
    unsigned long long r;
    asm("mov.b64 %0, {%1,%2};" : "=l"(r) : "f"(a), "f"(b));
    return r;
}
__device__ __forceinline__ void upk2(unsigned long long v, float& a, float& b) {
    asm("mov.b64 {%0,%1}, %2;" : "=f"(a), "=f"(b) : "l"(v));
}
#define FMA2(acc, a, b) asm("fma.rn.f32x2 %0, %1, %2, %0;" : "+l"(acc) : "l"(a), "l"(b))

// ============ k_rv: (fused) mixing weights w, r1, and ray2v — block per r ============
__global__ void __launch_bounds__(256) k_rv(const float* __restrict__ pref,
                                            const float* __restrict__ wm1_w, const float* __restrict__ wm1_b,
                                            const float* __restrict__ wm2_w, const float* __restrict__ wm2_b,
                                            const float* __restrict__ ray0_w, const float* __restrict__ ray0_b,
                                            const float* __restrict__ ray2_w, const float* __restrict__ ray2_b) {
    int r = blockIdx.x;
    __shared__ float sw[C_];
    __shared__ float sr1[RH_];
    __shared__ float sbias[D_];
    int t = threadIdx.x;
    if (t == 0) {
        float p0 = pref[r * 2], p1 = pref[r * 2 + 1];
        float h[16];
        #pragma unroll
        for (int j = 0; j < 16; j++) {
            float a = p0 * wm1_w[j * 2] + p1 * wm1_w[j * 2 + 1] + wm1_b[j];
            h[j] = a > 0.f ? a : 0.f;
        }
        float s = 0.f; float wr[C_];
        #pragma unroll
        for (int c = 0; c < C_; c++) {
            float a = wm2_b[c];
            #pragma unroll
            for (int j = 0; j < 16; j++) a += h[j] * wm2_w[c * 16 + j];
            wr[c] = 1.f / (1.f + expf(-a));
            s += wr[c];
        }
        float inv = 1.f / s;
        #pragma unroll
        for (int c = 0; c < C_; c++) { wr[c] *= inv; sw[c] = wr[c]; g_w[r][c] = wr[c]; }
    }
    __syncthreads();
    if (t < RH_) {
        float p0 = pref[r * 2], p1 = pref[r * 2 + 1];
        float a = 0.f;
        #pragma unroll
        for (int c = 0; c < C_; c++) {
            float2 rw = __ldg((const float2*)(ray0_w + (c * RH_ + t) * 2));
            a += sw[c] * (p0 * rw.x + p1 * rw.y + __ldg(ray0_b + c * RH_ + t));
        }
        sr1[t] = a > 0.f ? a : 0.f;
    }
    if (t >= 64 && t < 64 + D_) {
        int d = t - 64;
        float b = 0.f;
        #pragma unroll
        for (int c = 0; c < C_; c++) b += sw[c] * __ldg(ray2_b + c * D_ + d);
        sbias[d] = b;
    }
    __syncthreads();
    int warp = t >> 5, lane = t & 31;
    float r1a = sr1[lane], r1b = sr1[lane + 32];
    float acc[16];
    #pragma unroll
    for (int oi = 0; oi < 16; oi++) acc[oi] = 0.f;
    #pragma unroll
    for (int c = 0; c < C_; c++) {
        float wc = sw[c];
        #pragma unroll
        for (int oi = 0; oi < 16; oi++) {
            int o = warp * 16 + oi;
            const float* row = ray2_w + ((size_t)(c * D_ + o)) * RH_;
            acc[oi] += wc * (__ldg(row + lane) * r1a + __ldg(row + lane + 32) * r1b);
        }
    }
    #pragma unroll
    for (int oi = 0; oi < 16; oi++) {
        float s = acc[oi];
        #pragma unroll
        for (int off = 16; off > 0; off >>= 1) s += __shfl_down_sync(0xffffffffu, s, off);
        if (lane == 0) g_rv[r][warp * 16 + oi] = s + sbias[warp * 16 + oi];
    }
}

// ============ k_w2b1: W2[r,h] / b1[r,h] — block per (r,kind) ============
__global__ void __launch_bounds__(256) k_w2b1(const float* __restrict__ fc2_w,
                                              const float* __restrict__ fc2_b,
                                              const float* __restrict__ b1_w,
                                              const float* __restrict__ b1_b) {
    int r = blockIdx.x & 15, kind = blockIdx.x >> 4;
    const float* Wc = kind ? b1_w : fc2_w;
    const float* bc = kind ? b1_b : fc2_b;
    __shared__ float sw[C_];
    __shared__ float sbias[HID_];
    int t = threadIdx.x;
    if (t < C_) sw[t] = g_w[r][t];
    __syncthreads();
    if (t < HID_) {
        float b = 0.f;
        #pragma unroll
        for (int c = 0; c < C_; c++) b += sw[c] * __ldg(bc + c * HID_ + t);
        sbias[t] = b;
    }
    __syncthreads();
    int warp = t >> 5, lane = t & 31;
    float4 rv4 = *(const float4*)&g_rv[r][lane * 4];
    float acc[16];
    #pragma unroll
    for (int oi = 0; oi < 16; oi++) acc[oi] = 0.f;
    #pragma unroll
    for (int c = 0; c < C_; c++) {
        float wc = sw[c];
        #pragma unroll
        for (int oi = 0; oi < 16; oi++) {
            int o = warp * 16 + oi;
            float4 v = __ldg((const float4*)(Wc + ((size_t)(c * HID_ + o)) * D_) + lane);
            acc[oi] += wc * (v.x * rv4.x + v.y * rv4.y + v.z * rv4.z + v.w * rv4.w);
        }
    }
    #pragma unroll
    for (int oi = 0; oi < 16; oi++) {
        float s = acc[oi];
        #pragma unroll
        for (int off = 16; off > 0; off >>= 1) s += __shfl_down_sync(0xffffffffu, s, off);
        if (lane == 0) {
            int o = warp * 16 + oi;
            if (kind) g_b1[r][o] = s + sbias[o]; else g_W2[r][o] = s + sbias[o];
        }
    }
}

// ============ k_prep: beff (block 0) + P fill (16 blocks) ============
__global__ void k_prep(const float* __restrict__ b2_w, const float* __restrict__ b2_b) {
    int t = threadIdx.x;  // 512
    if (blockIdx.x == 0) {
        int warp = t >> 5, lane = t & 31;
        int r = warp;
        float4 rv4 = *(const float4*)&g_rv[r][lane * 4];
        float acc = 0.f;
        #pragma unroll
        for (int c = 0; c < C_; c++) {
            float wc = g_w[r][c];
            float4 bw = __ldg((const float4*)(b2_w + c * D_) + lane);
            acc += wc * (bw.x * rv4.x + bw.y * rv4.y + bw.z * rv4.z + bw.w * rv4.w);
            if (lane == 0) acc += wc * __ldg(b2_b + c);
        }
        float4 w24 = *(const float4*)&g_W2[r][lane * 4];
        float4 b14 = *(const float4*)&g_b1[r][lane * 4];
        acc += w24.x * b14.x + w24.y * b14.y + w24.z * b14.z + w24.w * b14.w;
        #pragma unroll
        for (int off = 16; off > 0; off >>= 1) acc += __shfl_down_sync(0xffffffffu, acc, off);
        if (lane == 0) g_beff[r] = acc;
    }
    int chbase = blockIdx.x * (CH_ / 16);
    for (int idx = t; idx < (CH_ / 16) * R_; idx += 512) {
        int ch = chbase + (idx >> 4), rr = idx & 15;
        g_P[ch][rr] = g_w[rr][ch >> 7] * g_W2[rr][ch & 127];
    }
}

// ============ k_weff: stream fc1_w (335 MB) -> Weff. One block per f. ============
// fc1_w flattens to [ch][f][d]: offset = ch*65536 + f*128 + d.
// 4 warps: warp = (chgrp<<1)|dhalf. Each lane owns 2 d's. acc = 16 u64 (no spill).
__global__ void __launch_bounds__(128, 4) k_weff(const float* __restrict__ fc1_w) {
    int f = blockIdx.x;
    int warp = threadIdx.x >> 5, lane = threadIdx.x & 31;
    int dhalf = warp & 1, chgrp = warp >> 1;
    const float* base = fc1_w + (size_t)f * 128 + dhalf * 64 + lane * 2;
    unsigned long long acc[8][2];
    #pragma unroll
    for (int rp = 0; rp < 8; rp++) { acc[rp][0] = 0ull; acc[rp][1] = 0ull; }

    int cb0 = chgrp * 4;
    float2 v[4], vn[4];
    #pragma unroll
    for (int q = 0; q < 4; q++)
        v[q] = __ldg((const float2*)(base + (size_t)(cb0 + q) * 65536u));

    for (int cb = cb0; cb < CH_; cb += 8) {
        int nb = cb + 8;
        if (nb < CH_) {
            #pragma unroll
            for (int q = 0; q < 4; q++)
                vn[q] = __ldg((const float2*)(base + (size_t)(nb + q) * 65536u));
        }
        #pragma unroll
        for (int q = 0; q < 4; q++) {
            int ch = cb + q;
            const ulonglong2* pp = (const ulonglong2*)g_P[ch];
            ulonglong2 pA = __ldg(pp + 0);
            ulonglong2 pB = __ldg(pp + 1);
            ulonglong2 pC = __ldg(pp + 2);
            ulonglong2 pD = __ldg(pp + 3);
            unsigned long long ux = pk2(v[q].x, v[q].x);
            unsigned long long uy = pk2(v[q].y, v[q].y);
            FMA2(acc[0][0], ux, pA.x); FMA2(acc[0][1], uy, pA.x);
            FMA2(acc[1][0], ux, pA.y); FMA2(acc[1][1], uy, pA.y);
            FMA2(acc[2][0], ux, pB.x); FMA2(acc[2][1], uy, pB.x);
            FMA2(acc[3][0], ux, pB.y); FMA2(acc[3][1], uy, pB.y);
            FMA2(acc[4][0], ux, pC.x); FMA2(acc[4][1], uy, pC.x);
            FMA2(acc[5][0], ux, pC.y); FMA2(acc[5][1], uy, pC.y);
            FMA2(acc[6][0], ux, pD.x); FMA2(acc[6][1], uy, pD.x);
            FMA2(acc[7][0], ux, pD.y); FMA2(acc[7][1], uy, pD.y);
        }
        #pragma unroll
        for (int q = 0; q < 4; q++) v[q] = vn[q];
    }
    // epilogue: weight by rv[r][d], reduce over lanes then warps
    int d0 = dhalf * 64 + lane * 2;
    float accr[16];
    #pragma unroll
    for (int r = 0; r < 16; r++) accr[r] = 0.f;
    #pragma unroll
    for (int rp = 0; rp < 8; rp++) {
        #pragma unroll
        for (int j = 0; j < 2; j++) {
            float a0, a1; upk2(acc[rp][j], a0, a1);
            accr[2 * rp]     += a0 * g_rv[2 * rp][d0 + j];
            accr[2 * rp + 1] += a1 * g_rv[2 * rp + 1][d0 + j];
        }
    }
    #pragma unroll
    for (int off = 16; off > 0; off >>= 1)
        #pragma unroll
        for (int r = 0; r < 16; r++)
            accr[r] += __shfl_down_sync(0xffffffffu, accr[r], off);
    __shared__ float sred[4][16];
    if (lane == 0) {
        #pragma unroll
        for (int r = 0; r < 16; r++) sred[warp][r] = accr[r];
    }
    __syncthreads();
    if (threadIdx.x < 16) {
        float s = sred[0][threadIdx.x] + sred[1][threadIdx.x]
                + sred[2][threadIdx.x] + sred[3][threadIdx.x];
        g_Weff[threadIdx.x][f] = s;
    }
}

// ============ k_weff_bias: += fc1_b contribution. fc1_b[ch*512+f] ============
__global__ void __launch_bounds__(128) k_weff_bias(const float* __restrict__ fc1_b) {
    int f = blockIdx.x, t = threadIdx.x;
    unsigned long long acc[8];
    #pragma unroll
    for (int rp = 0; rp < 8; rp++) acc[rp] = 0ull;
    for (int ch = t; ch < CH_; ch += 128) {
        float v = __ldg(fc1_b + (size_t)ch * 512u + f);
        unsigned long long vv = pk2(v, v);
        const ulonglong2* pp = (const ulonglong2*)g_P[ch];
        ulonglong2 pA = __ldg(pp + 0);
        ulonglong2 pB = __ldg(pp + 1);
        ulonglong2 pC = __ldg(pp + 2);
        ulonglong2 pD = __ldg(pp + 3);
        FMA2(acc[0], vv, pA.x); FMA2(acc[1], vv, pA.y);
        FMA2(acc[2], vv, pB.x); FMA2(acc[3], vv, pB.y);
        FMA2(acc[4], vv, pC.x); FMA2(acc[5], vv, pC.y);
        FMA2(acc[6], vv, pD.x); FMA2(acc[7], vv, pD.y);
    }
    float accr[16];
    #pragma unroll
    for (int rp = 0; rp < 8; rp++) upk2(acc[rp], accr[2 * rp], accr[2 * rp + 1]);
    #pragma unroll
    for (int off = 16; off > 0; off >>= 1)
        #pragma unroll
        for (int r = 0; r < 16; r++)
            accr[r] += __shfl_down_sync(0xffffffffu, accr[r], off);
    __shared__ float sred[4][16];
    int warp = t >> 5, lane = t & 31;
    if (lane == 0) {
        #pragma unroll
        for (int r = 0; r < 16; r++) sred[warp][r] = accr[r];
    }
    __syncthreads();
    if (t < 16) {
        float s = sred[0][t] + sred[1][t] + sred[2][t] + sred[3][t];
        g_Weff[t][f] += s;
    }
}

// ============ k_wx: fold Weff into base_w -> Wx partials ============
__global__ void __launch_bounds__(128) k_wx(const float* __restrict__ base_w) {
    __shared__ __align__(16) float sW[64][16];
    int i = blockIdx.x * 128 + threadIdx.x;
    int f0 = blockIdx.y * 64;
    for (int idx = threadIdx.x; idx < 64 * 16; idx += 128) {
        int ff = idx >> 4, r = idx & 15;
        sW[ff][r] = g_Weff[r][f0 + ff];
    }
    __syncthreads();
    unsigned long long acc[8];
    #pragma unroll
    for (int rp = 0; rp < 8; rp++) acc[rp] = 0ull;
    #pragma unroll 4
    for (int ff = 0; ff < 64; ff++) {
        float bw = __ldg(base_w + (size_t)(f0 + ff) * IN_ + i);
        unsigned long long b2 = pk2(bw, bw);
        const unsigned long long* pw = (const unsigned long long*)sW[ff];
        #pragma unroll
        for (int rp = 0; rp < 8; rp++) {
            unsigned long long tt = pw[rp];
            FMA2(acc[rp], b2, tt);
        }
    }
    float* o = &g_WxPart[blockIdx.y][i][0];
    #pragma unroll
    for (int rp = 0; rp < 8; rp++) {
        float a, b; upk2(acc[rp], a, b);
        o[2 * rp] = a; o[2 * rp + 1] = b;
    }
}

// ============ k_wx_reduce: sum partials + cst[r] ============
__global__ void k_wx_reduce(const float* __restrict__ base_b) {
    int idx = blockIdx.x * 256 + threadIdx.x;
    if (idx < IN_ * R_) {
        int i = idx >> 4, r = idx & 15;
        float s = 0.f;
        #pragma unroll
        for (int p = 0; p < 8; p++) s += g_WxPart[p][i][r];
        g_WxT[i][r] = s;
    }
    if (blockIdx.x == 0) {
        int warp = threadIdx.x >> 5, lane = threadIdx.x & 31;
        #pragma unroll
        for (int rr = warp; rr < R_; rr += 8) {
            float a = 0.f;
            #pragma unroll
            for (int kk = 0; kk < 16; kk++) {
                int ff = kk * 32 + lane;
                a += g_Weff[rr][ff] * __ldg(base_b + ff);
            }
            #pragma unroll
            for (int off = 16; off > 0; off >>= 1) a += __shfl_down_sync(0xffffffffu, a, off);
            if (lane == 0) g_cst[rr] = g_beff[rr] + a;
        }
    }
}

// ============ k_out: out[r,b] = x[b]·Wx[r] + cst[r]; 2 b per warp ============
__global__ void __launch_bounds__(256) k_out(const float* __restrict__ x,
                                             float* __restrict__ out, int write_raw) {
    int warp = threadIdx.x >> 5, lane = threadIdx.x & 31;
    int b0 = (blockIdx.x * 8 + warp) * 2;
    unsigned long long acc[2][8];
    #pragma unroll
    for (int j = 0; j < 2; j++)
        #pragma unroll
        for (int rp = 0; rp < 8; rp++) acc[j][rp] = 0ull;

    #pragma unroll
    for (int k = 0; k < 8; k++) {
        float4 xv0 = __ldg((const float4*)(x + (size_t)(b0 + 0) * IN_) + k * 32 + lane);
        float4 xv1 = __ldg((const float4*)(x + (size_t)(b0 + 1) * IN_) + k * 32 + lane);
        int ib = (k * 32 + lane) * 4;
        #pragma unroll
        for (int di = 0; di < 4; di++) {
            const ulonglong2* wr = (const ulonglong2*)g_WxT[ib + di];
            ulonglong2 wA = __ldg(wr + 0), wB = __ldg(wr + 1);
            ulonglong2 wC = __ldg(wr + 2), wD = __ldg(wr + 3);
            float x0c = di == 0 ? xv0.x : di == 1 ? xv0.y : di == 2 ? xv0.z : xv0.w;
            float x1c = di == 0 ? xv1.x : di == 1 ? xv1.y : di == 2 ? xv1.z : xv1.w;
            unsigned long long u0 = pk2(x0c, x0c), u1 = pk2(x1c, x1c);
            FMA2(acc[0][0], u0, wA.x); FMA2(acc[0][1], u0, wA.y);
            FMA2(acc[0][2], u0, wB.x); FMA2(acc[0][3], u0, wB.y);
            FMA2(acc[0][4], u0, wC.x); FMA2(acc[0][5], u0, wC.y);
            FMA2(acc[0][6], u0, wD.x); FMA2(acc[0][7], u0, wD.y);
            FMA2(acc[1][0], u1, wA.x); FMA2(acc[1][1], u1, wA.y);
            FMA2(acc[1][2], u1, wB.x); FMA2(acc[1][3], u1, wB.y);
            FMA2(acc[1][4], u1, wC.x); FMA2(acc[1][5], u1, wC.y);
            FMA2(acc[1][6], u1, wD.x); FMA2(acc[1][7], u1, wD.y);
        }
    }
    float accr[2][16];
    #pragma unroll
    for (int j = 0; j < 2; j++)
        #pragma unroll
        for (int rp = 0; rp < 8; rp++) upk2(acc[j][rp], accr[j][2 * rp], accr[j][2 * rp + 1]);
    #pragma unroll
    for (int off = 16; off > 0; off >>= 1)
        #pragma unroll
        for (int j = 0; j < 2; j++)
            #pragma unroll
            for (int r = 0; r < 16; r++)
                accr[j][r] += __shfl_down_sync(0xffffffffu, accr[j][r], off);
    if (lane == 0) {
        #pragma unroll
        for (int j = 0; j < 2; j++) {
            #pragma unroll
            for (int r = 0; r < 16; r++) {
                float v = accr[j][r] + g_cst[r];
                out[r * B_ + b0 + j] = 1.f / (1.f + expf(-v));
                if (write_raw) out[R_ * B_ + r * B_ + b0 + j] = v;
            }
        }
    }
}

// ---------------- launcher ----------------
extern "C" void kernel_launch(void* const* d_in, const int* in_sizes, int n_in,
                              void* d_out, int out_size) {
    const float* x      = (const float*)d_in[0];
    const float* pref   = (const float*)d_in[1];
    const float* base_w = (const float*)d_in[2];
    const float* base_b = (const float*)d_in[3];
    const float* wm1_w  = (const float*)d_in[4];
    const float* wm1_b  = (const float*)d_in[5];
    const float* wm2_w  = (const float*)d_in[6];
    const float* wm2_b  = (const float*)d_in[7];
    const float* ray0_w = (const float*)d_in[8];
    const float* ray0_b = (const float*)d_in[9];
    const float* ray2_w = (const float*)d_in[10];
    const float* ray2_b = (const float*)d_in[11];
    const float* fc1_w  = (const float*)d_in[12];
    const float* fc1_b  = (const float*)d_in[13];
    const float* b1_w   = (const float*)d_in[14];
    const float* b1_b   = (const float*)d_in[15];
    const float* fc2_w  = (const float*)d_in[16];
    const float* fc2_b  = (const float*)d_in[17];
    const float* b2_w   = (const float*)d_in[18];
    const float* b2_b   = (const float*)d_in[19];
    float* out = (float*)d_out;
    int write_raw = (out_size >= 2 * R_ * B_) ? 1 : 0;

    k_rv<<<R_, 256>>>(pref, wm1_w, wm1_b, wm2_w, wm2_b,
                      ray0_w, ray0_b, ray2_w, ray2_b);
    k_w2b1<<<32, 256>>>(fc2_w, fc2_b, b1_w, b1_b);
    k_prep<<<16, 512>>>(b2_w, b2_b);
    k_weff<<<F_, 128>>>(fc1_w);
    k_weff_bias<<<F_, 128>>>(fc1_b);
    dim3 g6(8, 8);
    k_wx<<<g6, 128>>>(base_w);
    k_wx_reduce<<<64, 256>>>(base_b);
    k_out<<<B_ / 16, 256>>>(x, out, write_raw);
}